// round 9
// baseline (speedup 1.0000x reference)
#include <cuda_runtime.h>
#include <math.h>

typedef unsigned long long ull;

#define G    8
#define NT   1024
#define XSTR 388
#define PSTR 388

#define RT_OFF   0
#define QS_OFF   2048
#define PY_OFF   4096
#define XS_OFF   (PY_OFF + 24832)
#define XS1_OFF  (XS_OFF + 12416)
#define WT_OFF   (XS_OFF + 24832)         // [32 s][8 h]
#define RD1_OFF  (WT_OFF + 256)
#define RD2_OFF  (RD1_OFF + 64)
#define MU_OFF   (RD2_OFF + 64)
#define RS_OFF   (MU_OFF + 8)
#define CODE_OFF (RS_OFF + 8)
#define LST_OFF  (CODE_OFF + 256)
#define MS_OFF   (LST_OFF + 256)
#define SMEM_FLOATS (MS_OFF + 8)
#define SMEM_BYTES  (SMEM_FLOATS * 4)

__device__ __forceinline__ float wsum(float v) {
#pragma unroll
    for (int o = 16; o > 0; o >>= 1) v += __shfl_xor_sync(0xffffffffu, v, o);
    return v;
}
__device__ __forceinline__ float wmax(float v) {
#pragma unroll
    for (int o = 16; o > 0; o >>= 1) v = fmaxf(v, __shfl_xor_sync(0xffffffffu, v, o));
    return v;
}
__device__ __forceinline__ void fma2(ull& d, ull a, ull b) {
    asm("fma.rn.f32x2 %0, %1, %2, %0;" : "+l"(d) : "l"(a), "l"(b));
}
__device__ __forceinline__ ull add2(ull a, ull b) {
    ull r; asm("add.rn.f32x2 %0, %1, %2;" : "=l"(r) : "l"(a), "l"(b)); return r;
}
__device__ __forceinline__ ull pack2(float v) {
    ull r; asm("mov.b64 %0, {%1, %1};" : "=l"(r) : "r"(__float_as_uint(v))); return r;
}
__device__ __forceinline__ ull pk(float a, float b) {
    ull r; asm("mov.b64 %0, {%1, %2};" : "=l"(r) : "r"(__float_as_uint(a)), "r"(__float_as_uint(b))); return r;
}
__device__ __forceinline__ float2 unpk(ull a) {
    float2 f; asm("mov.b64 {%0, %1}, %2;" : "=f"(f.x), "=f"(f.y) : "l"(a)); return f;
}
__device__ __forceinline__ float sum2(ull a) { float2 f = unpk(a); return f.x + f.y; }
__device__ __forceinline__ void cpasync16(void* dst, const void* src) {
    unsigned d = (unsigned)__cvta_generic_to_shared(dst);
    asm volatile("cp.async.cg.shared.global [%0], [%1], 16;\n" :: "r"(d), "l"(src));
}
__device__ __forceinline__ void cpcommit() { asm volatile("cp.async.commit_group;\n" ::: "memory"); }
__device__ __forceinline__ void cpwaitall() { asm volatile("cp.async.wait_group 0;\n" ::: "memory"); }

__device__ __forceinline__ void prefetchXc(float* Xbuf, long long b,
                                           const int* lst, int m,
                                           const float4* nn4, const float4* ed4, const float4* et4,
                                           int start, int stride) {
    int total = m * 96;
    for (int idx = start; idx < total; idx += stride) {
        int sp = idx / 96, c4 = idx - sp * 96;
        long long rb = (b * 32 + lst[sp]) * 32;
        const float4* src = (c4 < 32) ? nn4 + rb + c4
                          : (c4 < 64) ? ed4 + rb + (c4 - 32)
                                      : et4 + rb + (c4 - 64);
        cpasync16(&Xbuf[sp * XSTR + c4 * 4], src);
    }
}

__global__ __launch_bounds__(NT, 1)
void ta_kernel(const float* __restrict__ node, const float* __restrict__ timef,
               const float* __restrict__ edge, const float* __restrict__ nnode,
               const float* __restrict__ ntime, const int* __restrict__ mask,
               const float* __restrict__ WQ, const float* __restrict__ WKV,
               const float* __restrict__ WO, const float* __restrict__ bO,
               const float* __restrict__ gamma, const float* __restrict__ beta,
               float* __restrict__ out, int B)
{
    extern __shared__ float smf[];
    float* RT  = smf + RT_OFF;
    float* Qs  = smf + QS_OFF;
    float* PY  = smf + PY_OFF;
    float* XS  = smf + XS_OFF;
    float* XS1 = smf + XS1_OFF;
    float* Wt  = smf + WT_OFF;
    float* red1 = smf + RD1_OFF;
    float* red2 = smf + RD2_OFF;
    float* muS = smf + MU_OFF;
    float* rsS = smf + RS_OFF;
    int* codeS = (int*)(smf + CODE_OFF);
    int* lstS  = (int*)(smf + LST_OFF);
    int* mS    = (int*)(smf + MS_OFF);

    const int t = threadIdx.x;
    const int wid = t >> 5, lane = t & 31;
    const int b0 = blockIdx.x * G;
    const float4* nn4 = (const float4*)nnode;
    const float4* ed4 = (const float4*)edge;
    const float4* et4 = (const float4*)ntime;

    // phase 0a: masks + compaction
    if (t < 256) {
        int g = wid;
        int bb = b0 + g; if (bb > B - 1) bb = B - 1;
        int mk = mask[(long long)bb * 32 + lane];
        unsigned bal = __ballot_sync(0xffffffffu, mk != 0);
        int m = __popc(bal);
        if (m == 0) {
            codeS[g * 32 + lane] = 2;
            lstS[g * 32 + lane] = lane;
            if (lane == 0) mS[g] = 32;
        } else {
            codeS[g * 32 + lane] = mk ? 0 : 1;
            if (mk) lstS[g * 32 + __popc(bal & ((1u << lane) - 1u))] = lane;
            if (lane == 0) mS[g] = m;
        }
    }
    __syncthreads();

    // prefetch X[0]
    {
        int bb = b0; if (bb > B - 1) bb = B - 1;
        prefetchXc(XS, (long long)bb, &lstS[0], mS[0], nn4, ed4, et4, t, NT);
        cpcommit();
    }

    // phase 0b: RT
    for (int idx = t; idx < G * 256; idx += NT) {
        int g = idx & 7, j = idx >> 3;
        int bb = b0 + g; if (bb > B - 1) bb = B - 1;
        long long b = bb;
        RT[j * G + g] = (j < 128) ? node[b * 128 + j] : timef[b * 128 + (j - 128)];
    }
    __syncthreads();

    // phase 1: Q partials
    {
        const int o = t & 255, q = t >> 8;
        ull a0 = 0, a1 = 0, a2 = 0, a3 = 0;
        const int i0 = q * 64;
        const ull* RT2 = (const ull*)RT;
#pragma unroll 4
        for (int ii = 0; ii < 64; ++ii) {
            int i = i0 + ii;
            ull w2 = pack2(__ldg(&WQ[i * 256 + o]));
            ulonglong2 ra = *(const ulonglong2*)&RT2[i * 4];
            ulonglong2 rb = *(const ulonglong2*)&RT2[i * 4 + 2];
            fma2(a0, ra.x, w2); fma2(a1, ra.y, w2);
            fma2(a2, rb.x, w2); fma2(a3, rb.y, w2);
        }
        ull* stg = (ull*)(XS1 + q * 2048 + o * 8);
        ((ulonglong2*)stg)[0] = make_ulonglong2(a0, a1);
        ((ulonglong2*)stg)[1] = make_ulonglong2(a2, a3);
    }
    __syncthreads();
    {
        const ull* S = (const ull*)XS1;
        ((ull*)Qs)[t] = add2(add2(S[t], S[1024 + t]), add2(S[2048 + t], S[3072 + t]));
    }
    __syncthreads();

    // phase 2: P[g][h][i], coalesced WKV
    {
        const int h = wid >> 2, ic = wid & 3;
        const int il = lane >> 3, q = lane & 7;
        const int q1 = q & 1, q2 = (q >> 1) & 1, q4 = (q >> 2) & 1;
        ull Qp[4][4];
        const ull* Q2 = (const ull*)Qs;
#pragma unroll
        for (int e = 0; e < 4; ++e) {
            int c = h * 32 + q * 4 + e;
            ulonglong2 qa = *(const ulonglong2*)&Q2[c * 4];
            ulonglong2 qb = *(const ulonglong2*)&Q2[c * 4 + 2];
            Qp[e][0] = qa.x; Qp[e][1] = qa.y; Qp[e][2] = qb.x; Qp[e][3] = qb.y;
        }
        const int ibase = ic * 96 + il;
#pragma unroll 2
        for (int it = 0; it < 24; ++it) {
            int i = ibase + it * 4;
            float4 wv = __ldg((const float4*)&WKV[(size_t)i * 512 + h * 32 + q * 4]);
            ull acc[4] = {0, 0, 0, 0};
#pragma unroll
            for (int e = 0; e < 4; ++e) {
                ull wp = pack2((&wv.x)[e]);
                fma2(acc[0], Qp[e][0], wp); fma2(acc[1], Qp[e][1], wp);
                fma2(acc[2], Qp[e][2], wp); fma2(acc[3], Qp[e][3], wp);
            }
            float v[8];
#pragma unroll
            for (int p = 0; p < 4; ++p) { float2 f = unpk(acc[p]); v[2*p] = f.x; v[2*p+1] = f.y; }
            float u[4];
#pragma unroll
            for (int j = 0; j < 4; ++j) {
                float a = v[2*j], b = v[2*j+1];
                float mine = q1 ? b : a, send = q1 ? a : b;
                u[j] = mine + __shfl_xor_sync(0xffffffffu, send, 1);
            }
            float w2_[2];
#pragma unroll
            for (int kk = 0; kk < 2; ++kk) {
                float a = u[2*kk], b = u[2*kk+1];
                float mine = q2 ? b : a, send = q2 ? a : b;
                w2_[kk] = mine + __shfl_xor_sync(0xffffffffu, send, 2);
            }
            float a = w2_[0], b = w2_[1];
            float mine = q4 ? b : a, send = q4 ? a : b;
            PY[(q * 8 + h) * PSTR + i] = mine + __shfl_xor_sync(0xffffffffu, send, 4);
        }
    }
    cpwaitall();
    __syncthreads();

    // phase 3: pipelined — interval k: scores(k) [w0-23] || Y(k-1)+prefetch [w24-29]
    float* AttP = Qs;
#pragma unroll 1
    for (int k = 0; k <= G; ++k) {
        if (wid < 24) {
            if (k < G) {
                const int m = mS[k];
                float* Xbuf = XS + (k & 1) * 12416;
                const int sq0 = wid >> 2, iq = wid & 3;
                const int h = lane >> 2, sl = lane & 3;
#pragma unroll 1
                for (int sq = sq0; sq * 4 < m; sq += 6) {
                    int sp = sq * 4 + sl;
                    bool valid = sp < m;
                    int spc = valid ? sp : (m - 1);
                    const ulonglong2* X2 = (const ulonglong2*)&Xbuf[spc * XSTR + iq * 96];
                    const ulonglong2* P2 = (const ulonglong2*)&PY[(k * 8 + h) * PSTR + iq * 96];
                    ull a0 = 0, a1 = 0;
#pragma unroll
                    for (int j = 0; j < 24; j += 2) {
                        ulonglong2 x0 = X2[j], p0 = P2[j];
                        ulonglong2 x1 = X2[j + 1], p1 = P2[j + 1];
                        fma2(a0, x0.x, p0.x); fma2(a0, x0.y, p0.y);
                        fma2(a1, x1.x, p1.x); fma2(a1, x1.y, p1.y);
                    }
                    if (valid)
                        AttP[iq * 256 + lstS[k * 32 + sp] * 8 + h] = sum2(add2(a0, a1));
                }
            }
        } else if (wid < 30) {
            if (k >= 1) {
                // Y(k-1): 192 threads, col-pairs, 8 heads packed
                const int gm = k - 1, m = mS[gm];
                float* Xbuf = XS + (gm & 1) * 12416;
                const int col = (t - 768) * 2;
                ull acc[8] = {0,0,0,0,0,0,0,0};
#pragma unroll 2
                for (int sp = 0; sp < m; ++sp) {
                    int so = lstS[gm * 32 + sp];
                    ull x2 = *(const ull*)&Xbuf[sp * XSTR + col];
                    float4 wa = *(const float4*)&Wt[so * 8];
                    float4 wb = *(const float4*)&Wt[so * 8 + 4];
                    fma2(acc[0], x2, pack2(wa.x)); fma2(acc[1], x2, pack2(wa.y));
                    fma2(acc[2], x2, pack2(wa.z)); fma2(acc[3], x2, pack2(wa.w));
                    fma2(acc[4], x2, pack2(wb.x)); fma2(acc[5], x2, pack2(wb.y));
                    fma2(acc[6], x2, pack2(wb.z)); fma2(acc[7], x2, pack2(wb.w));
                }
#pragma unroll
                for (int h = 0; h < 8; ++h)
                    *(ull*)&PY[(gm * 8 + h) * PSTR + col] = acc[h];
            }
            // refill the buffer Y just consumed with X[k+1]
            asm volatile("bar.sync 2, 192;" ::: "memory");
            if (k < G - 1) {
                int bb = b0 + k + 1; if (bb > B - 1) bb = B - 1;
                prefetchXc(XS + ((k + 1) & 1) * 12416, (long long)bb,
                           &lstS[(k + 1) * 32], mS[k + 1], nn4, ed4, et4, t - 768, 192);
                cpcommit();
                cpwaitall();
            }
        }
        __syncthreads();
        // softmax(k) -> Wt [s][8h]
        if (k < G && wid < 8) {
            const int s = lane;
            int cde = codeS[k * 32 + s];
            float a = AttP[s * 8 + wid] + AttP[256 + s * 8 + wid]
                    + AttP[512 + s * 8 + wid] + AttP[768 + s * 8 + wid];
            float v = (cde == 0) ? a * 0.17677669529663687f
                                 : ((cde == 1) ? -1e10f : 0.f);
            float mx = wmax(v);
            float e = __expf(v - mx);
            float ss = wsum(e);
            Wt[s * 8 + wid] = e / ss;
        }
        __syncthreads();
    }

    // phase 4: O partials
    {
        const int o = t & 255, q = t >> 8, h = o >> 5;
        ull acc2[8];
#pragma unroll
        for (int g = 0; g < 8; ++g) acc2[g] = 0;
        const float* wvp = WKV + 256 + o;
        const int i0 = q * 96;
#pragma unroll 2
        for (int j = 0; j < 24; ++j) {
            int i = i0 + j * 4;
            float w0 = __ldg(&wvp[(size_t)(i + 0) * 512]);
            float w1 = __ldg(&wvp[(size_t)(i + 1) * 512]);
            float w2 = __ldg(&wvp[(size_t)(i + 2) * 512]);
            float w3 = __ldg(&wvp[(size_t)(i + 3) * 512]);
            ull wp01 = pk(w0, w1), wp23 = pk(w2, w3);
#pragma unroll
            for (int g = 0; g < 8; ++g) {
                ulonglong2 y = *(const ulonglong2*)&PY[(g * 8 + h) * PSTR + i];
                fma2(acc2[g], y.x, wp01);
                fma2(acc2[g], y.y, wp23);
            }
        }
        float r[8];
#pragma unroll
        for (int g = 0; g < 8; ++g) r[g] = sum2(acc2[g]);
        float* stg = XS + q * 2048 + o * 8;
        *(float4*)stg       = make_float4(r[0], r[1], r[2], r[3]);
        *(float4*)(stg + 4) = make_float4(r[4], r[5], r[6], r[7]);
    }
    __syncthreads();
    {
        const ull* S = (const ull*)XS;
        ((ull*)Qs)[t] = add2(add2(S[t], S[1024 + t]), add2(S[2048 + t], S[3072 + t]));
    }
    __syncthreads();

    // phase 5: out-proj partials
    {
        const int o = t & 255, q = t >> 8;
        ull a0 = 0, a1 = 0, a2 = 0, a3 = 0;
        const ull* O2 = (const ull*)Qs;
        const int i0 = q * 64;
#pragma unroll 4
        for (int ii = 0; ii < 64; ++ii) {
            int i = i0 + ii;
            ull wp = pack2(__ldg(&WO[i * 256 + o]));
            ulonglong2 va = *(const ulonglong2*)&O2[i * 4];
            ulonglong2 vb = *(const ulonglong2*)&O2[i * 4 + 2];
            fma2(a0, va.x, wp); fma2(a1, va.y, wp);
            fma2(a2, vb.x, wp); fma2(a3, vb.y, wp);
        }
        float2 f0 = unpk(a0), f1 = unpk(a1), f2 = unpk(a2), f3 = unpk(a3);
        float* stg = XS1 + q * 2048 + o * 8;
        *(float4*)stg       = make_float4(f0.x, f0.y, f1.x, f1.y);
        *(float4*)(stg + 4) = make_float4(f2.x, f2.y, f3.x, f3.y);
    }
    __syncthreads();

    // residual + LayerNorm
    {
        const int o = t & 255, gp = t >> 8;
        float xg[2];
#pragma unroll
        for (int j = 0; j < 2; ++j) {
            int g = gp * 2 + j;
            int idx = o * 8 + g;
            float s = XS1[idx] + XS1[2048 + idx] + XS1[4096 + idx] + XS1[6144 + idx];
            xg[j] = s + __ldg(&bO[o]) + RT[o * 8 + g];
            float s1 = wsum(xg[j]);
            float s2 = wsum(xg[j] * xg[j]);
            if (lane == 0) { red1[wid * 2 + j] = s1; red2[wid * 2 + j] = s2; }
        }
        __syncthreads();
        if (t < 8) {
            int g = t, gq = g >> 1, j = g & 1;
            float t1 = 0.f, t2 = 0.f;
#pragma unroll
            for (int w = 0; w < 8; ++w) {
                t1 += red1[(gq * 8 + w) * 2 + j];
                t2 += red2[(gq * 8 + w) * 2 + j];
            }
            float mu = t1 * (1.0f / 256.0f);
            float var = t2 * (1.0f / 256.0f) - mu * mu;
            muS[g] = mu;
            rsS[g] = rsqrtf(var + 1e-5f);
        }
        __syncthreads();
        float gm = __ldg(&gamma[o]), bt = __ldg(&beta[o]);
#pragma unroll
        for (int j = 0; j < 2; ++j) {
            int g = gp * 2 + j;
            int b = b0 + g;
            if (b < B)
                out[(size_t)b * 256 + o] = (xg[j] - muS[g]) * rsS[g] * gm + bt;
        }
    }
}

extern "C" void kernel_launch(void* const* d_in, const int* in_sizes, int n_in,
                              void* d_out, int out_size) {
    (void)n_in; (void)out_size;
    const float* node  = (const float*)d_in[0];
    const float* timef = (const float*)d_in[1];
    const float* edge  = (const float*)d_in[2];
    const float* nnode = (const float*)d_in[3];
    const float* ntime = (const float*)d_in[4];
    const int*   mask  = (const int*)d_in[5];
    const float* WQ    = (const float*)d_in[6];
    const float* WKV   = (const float*)d_in[7];
    const float* WO    = (const float*)d_in[8];
    const float* bO    = (const float*)d_in[9];
    const float* gamma = (const float*)d_in[10];
    const float* beta  = (const float*)d_in[11];
    float* out = (float*)d_out;

    int B = in_sizes[0] / 128;
    int blocks = (B + G - 1) / G;

    cudaFuncSetAttribute(ta_kernel, cudaFuncAttributeMaxDynamicSharedMemorySize, SMEM_BYTES);
    ta_kernel<<<blocks, NT, SMEM_BYTES>>>(node, timef, edge, nnode, ntime, mask,
                                          WQ, WKV, WO, bO, gamma, beta, out, B);
}

// round 10
// speedup vs baseline: 1.0814x; 1.0814x over previous
#include <cuda_runtime.h>
#include <math.h>

typedef unsigned long long ull;

#define G    8
#define NT   1024
#define XSTR 388
#define PSTR 388

#define RT_OFF   0
#define QS_OFF   2048                     // Q [o][g]; AttP [8][32][8]; OvT [o][g]
#define PY_OFF   4096
#define XS_OFF   (PY_OFF + 24832)
#define XS1_OFF  (XS_OFF + 12416)
#define WT_OFF   (XS_OFF + 24832)         // [32 s][8 h]
#define RD1_OFF  (WT_OFF + 256)
#define RD2_OFF  (RD1_OFF + 64)
#define MU_OFF   (RD2_OFF + 64)
#define RS_OFF   (MU_OFF + 8)
#define CODE_OFF (RS_OFF + 8)
#define LST_OFF  (CODE_OFF + 256)
#define MS_OFF   (LST_OFF + 256)
#define SMEM_FLOATS (MS_OFF + 8)
#define SMEM_BYTES  (SMEM_FLOATS * 4)

__device__ __forceinline__ float wsum(float v) {
#pragma unroll
    for (int o = 16; o > 0; o >>= 1) v += __shfl_xor_sync(0xffffffffu, v, o);
    return v;
}
__device__ __forceinline__ float wmax(float v) {
#pragma unroll
    for (int o = 16; o > 0; o >>= 1) v = fmaxf(v, __shfl_xor_sync(0xffffffffu, v, o));
    return v;
}
__device__ __forceinline__ void fma2(ull& d, ull a, ull b) {
    asm("fma.rn.f32x2 %0, %1, %2, %0;" : "+l"(d) : "l"(a), "l"(b));
}
__device__ __forceinline__ ull add2(ull a, ull b) {
    ull r; asm("add.rn.f32x2 %0, %1, %2;" : "=l"(r) : "l"(a), "l"(b)); return r;
}
__device__ __forceinline__ ull pack2(float v) {
    ull r; asm("mov.b64 %0, {%1, %1};" : "=l"(r) : "r"(__float_as_uint(v))); return r;
}
__device__ __forceinline__ ull pk(float a, float b) {
    ull r; asm("mov.b64 %0, {%1, %2};" : "=l"(r) : "r"(__float_as_uint(a)), "r"(__float_as_uint(b))); return r;
}
__device__ __forceinline__ float2 unpk(ull a) {
    float2 f; asm("mov.b64 {%0, %1}, %2;" : "=f"(f.x), "=f"(f.y) : "l"(a)); return f;
}
__device__ __forceinline__ float sum2(ull a) { float2 f = unpk(a); return f.x + f.y; }
__device__ __forceinline__ void cpasync16(void* dst, const void* src) {
    unsigned d = (unsigned)__cvta_generic_to_shared(dst);
    asm volatile("cp.async.cg.shared.global [%0], [%1], 16;\n" :: "r"(d), "l"(src));
}
__device__ __forceinline__ void cpcommit() { asm volatile("cp.async.commit_group;\n" ::: "memory"); }
__device__ __forceinline__ void cpwaitall() { asm volatile("cp.async.wait_group 0;\n" ::: "memory"); }

__device__ __forceinline__ void prefetchXc(float* Xbuf, long long b,
                                           const int* lst, int m,
                                           const float4* nn4, const float4* ed4, const float4* et4,
                                           int start, int stride) {
    int total = m * 96;
    for (int idx = start; idx < total; idx += stride) {
        int sp = idx / 96, c4 = idx - sp * 96;
        long long rb = (b * 32 + lst[sp]) * 32;
        const float4* src = (c4 < 32) ? nn4 + rb + c4
                          : (c4 < 64) ? ed4 + rb + (c4 - 32)
                                      : et4 + rb + (c4 - 64);
        cpasync16(&Xbuf[sp * XSTR + c4 * 4], src);
    }
}

__global__ __launch_bounds__(NT, 1)
void ta_kernel(const float* __restrict__ node, const float* __restrict__ timef,
               const float* __restrict__ edge, const float* __restrict__ nnode,
               const float* __restrict__ ntime, const int* __restrict__ mask,
               const float* __restrict__ WQ, const float* __restrict__ WKV,
               const float* __restrict__ WO, const float* __restrict__ bO,
               const float* __restrict__ gamma, const float* __restrict__ beta,
               float* __restrict__ out, int B)
{
    extern __shared__ float smf[];
    float* RT  = smf + RT_OFF;
    float* Qs  = smf + QS_OFF;
    float* PY  = smf + PY_OFF;
    float* XS  = smf + XS_OFF;
    float* XS1 = smf + XS1_OFF;
    float* Wt  = smf + WT_OFF;
    float* red1 = smf + RD1_OFF;
    float* red2 = smf + RD2_OFF;
    float* muS = smf + MU_OFF;
    float* rsS = smf + RS_OFF;
    int* codeS = (int*)(smf + CODE_OFF);
    int* lstS  = (int*)(smf + LST_OFF);
    int* mS    = (int*)(smf + MS_OFF);

    const int t = threadIdx.x;
    const int wid = t >> 5, lane = t & 31;
    const int b0 = blockIdx.x * G;
    const float4* nn4 = (const float4*)nnode;
    const float4* ed4 = (const float4*)edge;
    const float4* et4 = (const float4*)ntime;

    // phase 0a: masks + compaction
    if (t < 256) {
        int g = wid;
        int bb = b0 + g; if (bb > B - 1) bb = B - 1;
        int mk = mask[(long long)bb * 32 + lane];
        unsigned bal = __ballot_sync(0xffffffffu, mk != 0);
        int m = __popc(bal);
        if (m == 0) {
            codeS[g * 32 + lane] = 2;
            lstS[g * 32 + lane] = lane;
            if (lane == 0) mS[g] = 32;
        } else {
            codeS[g * 32 + lane] = mk ? 0 : 1;
            if (mk) lstS[g * 32 + __popc(bal & ((1u << lane) - 1u))] = lane;
            if (lane == 0) mS[g] = m;
        }
    }
    __syncthreads();

    // prefetch X[0]
    {
        int bb = b0; if (bb > B - 1) bb = B - 1;
        prefetchXc(XS, (long long)bb, &lstS[0], mS[0], nn4, ed4, et4, t, NT);
        cpcommit();
    }

    // phase 0b: RT
    for (int idx = t; idx < G * 256; idx += NT) {
        int g = idx & 7, j = idx >> 3;
        int bb = b0 + g; if (bb > B - 1) bb = B - 1;
        long long b = bb;
        RT[j * G + g] = (j < 128) ? node[b * 128 + j] : timef[b * 128 + (j - 128)];
    }
    __syncthreads();

    // phase 1: Q partials
    {
        const int o = t & 255, q = t >> 8;
        ull a0 = 0, a1 = 0, a2 = 0, a3 = 0;
        const int i0 = q * 64;
        const ull* RT2 = (const ull*)RT;
#pragma unroll 4
        for (int ii = 0; ii < 64; ++ii) {
            int i = i0 + ii;
            ull w2 = pack2(__ldg(&WQ[i * 256 + o]));
            ulonglong2 ra = *(const ulonglong2*)&RT2[i * 4];
            ulonglong2 rb = *(const ulonglong2*)&RT2[i * 4 + 2];
            fma2(a0, ra.x, w2); fma2(a1, ra.y, w2);
            fma2(a2, rb.x, w2); fma2(a3, rb.y, w2);
        }
        ull* stg = (ull*)(XS1 + q * 2048 + o * 8);
        ((ulonglong2*)stg)[0] = make_ulonglong2(a0, a1);
        ((ulonglong2*)stg)[1] = make_ulonglong2(a2, a3);
    }
    __syncthreads();
    {
        const ull* S = (const ull*)XS1;
        ((ull*)Qs)[t] = add2(add2(S[t], S[1024 + t]), add2(S[2048 + t], S[3072 + t]));
    }
    __syncthreads();

    // phase 2: P[g][h][i], coalesced WKV
    {
        const int h = wid >> 2, ic = wid & 3;
        const int il = lane >> 3, q = lane & 7;
        const int q1 = q & 1, q2 = (q >> 1) & 1, q4 = (q >> 2) & 1;
        ull Qp[4][4];
        const ull* Q2 = (const ull*)Qs;
#pragma unroll
        for (int e = 0; e < 4; ++e) {
            int c = h * 32 + q * 4 + e;
            ulonglong2 qa = *(const ulonglong2*)&Q2[c * 4];
            ulonglong2 qb = *(const ulonglong2*)&Q2[c * 4 + 2];
            Qp[e][0] = qa.x; Qp[e][1] = qa.y; Qp[e][2] = qb.x; Qp[e][3] = qb.y;
        }
        const int ibase = ic * 96 + il;
#pragma unroll 2
        for (int it = 0; it < 24; ++it) {
            int i = ibase + it * 4;
            float4 wv = __ldg((const float4*)&WKV[(size_t)i * 512 + h * 32 + q * 4]);
            ull acc[4] = {0, 0, 0, 0};
#pragma unroll
            for (int e = 0; e < 4; ++e) {
                ull wp = pack2((&wv.x)[e]);
                fma2(acc[0], Qp[e][0], wp); fma2(acc[1], Qp[e][1], wp);
                fma2(acc[2], Qp[e][2], wp); fma2(acc[3], Qp[e][3], wp);
            }
            float v[8];
#pragma unroll
            for (int p = 0; p < 4; ++p) { float2 f = unpk(acc[p]); v[2*p] = f.x; v[2*p+1] = f.y; }
            float u[4];
#pragma unroll
            for (int j = 0; j < 4; ++j) {
                float a = v[2*j], b = v[2*j+1];
                float mine = q1 ? b : a, send = q1 ? a : b;
                u[j] = mine + __shfl_xor_sync(0xffffffffu, send, 1);
            }
            float w2_[2];
#pragma unroll
            for (int kk = 0; kk < 2; ++kk) {
                float a = u[2*kk], b = u[2*kk+1];
                float mine = q2 ? b : a, send = q2 ? a : b;
                w2_[kk] = mine + __shfl_xor_sync(0xffffffffu, send, 2);
            }
            float a = w2_[0], b = w2_[1];
            float mine = q4 ? b : a, send = q4 ? a : b;
            PY[(q * 8 + h) * PSTR + i] = mine + __shfl_xor_sync(0xffffffffu, send, 4);
        }
    }
    cpwaitall();
    __syncthreads();

    // phase 3: per-g attention (R7 schedule)
    float* AttP = Qs;     // up to [8 iq][32 s][8 h] = 2048 floats
#pragma unroll 1
    for (int g = 0; g < G; ++g) {
        float* Xbuf = XS + (g & 1) * 12416;
        const int m = mS[g];

        if (g < G - 1) {
            int bb = b0 + g + 1; if (bb > B - 1) bb = B - 1;
            prefetchXc(XS + ((g + 1) & 1) * 12416, (long long)bb,
                       &lstS[(g + 1) * 32], mS[g + 1], nn4, ed4, et4, t, NT);
        }
        cpcommit();

        // scores: adaptive i-split
        if (m <= 16) {
            // 8-way: warp = (sq 0..3, iq 0..7); chunk = 48 floats (12 ulonglong2)
            const int sq = wid >> 3, iq = wid & 7;
            const int h = lane >> 2, sl = lane & 3;
            if (sq * 4 < m) {
                int sp = sq * 4 + sl;
                bool valid = sp < m;
                int spc = valid ? sp : (m - 1);
                const ulonglong2* X2 = (const ulonglong2*)&Xbuf[spc * XSTR + iq * 48];
                const ulonglong2* P2 = (const ulonglong2*)&PY[(g * 8 + h) * PSTR + iq * 48];
                ull a0 = 0, a1 = 0;
#pragma unroll
                for (int j = 0; j < 12; j += 2) {
                    ulonglong2 x0 = X2[j], p0 = P2[j];
                    ulonglong2 x1 = X2[j + 1], p1 = P2[j + 1];
                    fma2(a0, x0.x, p0.x); fma2(a0, x0.y, p0.y);
                    fma2(a1, x1.x, p1.x); fma2(a1, x1.y, p1.y);
                }
                if (valid)
                    AttP[iq * 256 + lstS[g * 32 + sp] * 8 + h] = sum2(add2(a0, a1));
            }
        } else {
            // 4-way: warp = (sq 0..7, iq 0..3); chunk = 96 floats
            const int sq = wid >> 2, iq = wid & 3;
            const int h = lane >> 2, sl = lane & 3;
            if (sq * 4 < m) {
                int sp = sq * 4 + sl;
                bool valid = sp < m;
                int spc = valid ? sp : (m - 1);
                const ulonglong2* X2 = (const ulonglong2*)&Xbuf[spc * XSTR + iq * 96];
                const ulonglong2* P2 = (const ulonglong2*)&PY[(g * 8 + h) * PSTR + iq * 96];
                ull a0 = 0, a1 = 0;
#pragma unroll
                for (int j = 0; j < 24; j += 2) {
                    ulonglong2 x0 = X2[j], p0 = P2[j];
                    ulonglong2 x1 = X2[j + 1], p1 = P2[j + 1];
                    fma2(a0, x0.x, p0.x); fma2(a0, x0.y, p0.y);
                    fma2(a1, x1.x, p1.x); fma2(a1, x1.y, p1.y);
                }
                if (valid)
                    AttP[iq * 256 + lstS[g * 32 + sp] * 8 + h] = sum2(add2(a0, a1));
            }
        }
        __syncthreads();

        // softmax: warp h (wid<8), lane = s; nq partials
        if (wid < 8) {
            const int s = lane;
            const int nq = (m <= 16) ? 8 : 4;
            int cde = codeS[g * 32 + s];
            float a = 0.f;
#pragma unroll 4
            for (int iq = 0; iq < nq; ++iq)
                a += AttP[iq * 256 + s * 8 + wid];
            float v = (cde == 0) ? a * 0.17677669529663687f
                                 : ((cde == 1) ? -1e10f : 0.f);
            float mx = wmax(v);
            float e = __expf(v - mx);
            float ss = wsum(e);
            Wt[s * 8 + wid] = e / ss;     // [s][8h]
        }
        __syncthreads();

        // Y[g][*][col]: 384 threads, broadcast head-pair weights
        if (t < 384) {
            const int col = t;
            ull acc0 = 0, acc1 = 0, acc2 = 0, acc3 = 0;
#pragma unroll 2
            for (int sp = 0; sp < m; ++sp) {
                int so = lstS[g * 32 + sp];
                ull x2 = pack2(Xbuf[sp * XSTR + col]);
                ulonglong2 wa = *(const ulonglong2*)&Wt[so * 8];
                ulonglong2 wb = *(const ulonglong2*)&Wt[so * 8 + 4];
                fma2(acc0, x2, wa.x);
                fma2(acc1, x2, wa.y);
                fma2(acc2, x2, wb.x);
                fma2(acc3, x2, wb.y);
            }
            float2 y01 = unpk(acc0), y23 = unpk(acc1);
            float2 y45 = unpk(acc2), y67 = unpk(acc3);
            PY[(g * 8 + 0) * PSTR + col] = y01.x;
            PY[(g * 8 + 1) * PSTR + col] = y01.y;
            PY[(g * 8 + 2) * PSTR + col] = y23.x;
            PY[(g * 8 + 3) * PSTR + col] = y23.y;
            PY[(g * 8 + 4) * PSTR + col] = y45.x;
            PY[(g * 8 + 5) * PSTR + col] = y45.y;
            PY[(g * 8 + 6) * PSTR + col] = y67.x;
            PY[(g * 8 + 7) * PSTR + col] = y67.y;
        }
        cpwaitall();
        __syncthreads();
    }

    // phase 4: O partials
    {
        const int o = t & 255, q = t >> 8, h = o >> 5;
        ull acc2[8];
#pragma unroll
        for (int g = 0; g < 8; ++g) acc2[g] = 0;
        const float* wvp = WKV + 256 + o;
        const int i0 = q * 96;
#pragma unroll 2
        for (int j = 0; j < 24; ++j) {
            int i = i0 + j * 4;
            float w0 = __ldg(&wvp[(size_t)(i + 0) * 512]);
            float w1 = __ldg(&wvp[(size_t)(i + 1) * 512]);
            float w2 = __ldg(&wvp[(size_t)(i + 2) * 512]);
            float w3 = __ldg(&wvp[(size_t)(i + 3) * 512]);
            ull wp01 = pk(w0, w1), wp23 = pk(w2, w3);
#pragma unroll
            for (int g = 0; g < 8; ++g) {
                ulonglong2 y = *(const ulonglong2*)&PY[(g * 8 + h) * PSTR + i];
                fma2(acc2[g], y.x, wp01);
                fma2(acc2[g], y.y, wp23);
            }
        }
        float r[8];
#pragma unroll
        for (int g = 0; g < 8; ++g) r[g] = sum2(acc2[g]);
        float* stg = XS + q * 2048 + o * 8;
        *(float4*)stg       = make_float4(r[0], r[1], r[2], r[3]);
        *(float4*)(stg + 4) = make_float4(r[4], r[5], r[6], r[7]);
    }
    __syncthreads();
    {
        const ull* S = (const ull*)XS;
        ((ull*)Qs)[t] = add2(add2(S[t], S[1024 + t]), add2(S[2048 + t], S[3072 + t]));
    }
    __syncthreads();

    // phase 5: out-proj partials
    {
        const int o = t & 255, q = t >> 8;
        ull a0 = 0, a1 = 0, a2 = 0, a3 = 0;
        const ull* O2 = (const ull*)Qs;
        const int i0 = q * 64;
#pragma unroll 4
        for (int ii = 0; ii < 64; ++ii) {
            int i = i0 + ii;
            ull wp = pack2(__ldg(&WO[i * 256 + o]));
            ulonglong2 va = *(const ulonglong2*)&O2[i * 4];
            ulonglong2 vb = *(const ulonglong2*)&O2[i * 4 + 2];
            fma2(a0, va.x, wp); fma2(a1, va.y, wp);
            fma2(a2, vb.x, wp); fma2(a3, vb.y, wp);
        }
        float2 f0 = unpk(a0), f1 = unpk(a1), f2 = unpk(a2), f3 = unpk(a3);
        float* stg = XS1 + q * 2048 + o * 8;
        *(float4*)stg       = make_float4(f0.x, f0.y, f1.x, f1.y);
        *(float4*)(stg + 4) = make_float4(f2.x, f2.y, f3.x, f3.y);
    }
    __syncthreads();

    // residual + LayerNorm
    {
        const int o = t & 255, gp = t >> 8;
        float xg[2];
#pragma unroll
        for (int j = 0; j < 2; ++j) {
            int g = gp * 2 + j;
            int idx = o * 8 + g;
            float s = XS1[idx] + XS1[2048 + idx] + XS1[4096 + idx] + XS1[6144 + idx];
            xg[j] = s + __ldg(&bO[o]) + RT[o * 8 + g];
            float s1 = wsum(xg[j]);
            float s2 = wsum(xg[j] * xg[j]);
            if (lane == 0) { red1[wid * 2 + j] = s1; red2[wid * 2 + j] = s2; }
        }
        __syncthreads();
        if (t < 8) {
            int g = t, gq = g >> 1, j = g & 1;
            float t1 = 0.f, t2 = 0.f;
#pragma unroll
            for (int w = 0; w < 8; ++w) {
                t1 += red1[(gq * 8 + w) * 2 + j];
                t2 += red2[(gq * 8 + w) * 2 + j];
            }
            float mu = t1 * (1.0f / 256.0f);
            float var = t2 * (1.0f / 256.0f) - mu * mu;
            muS[g] = mu;
            rsS[g] = rsqrtf(var + 1e-5f);
        }
        __syncthreads();
        float gm = __ldg(&gamma[o]), bt = __ldg(&beta[o]);
#pragma unroll
        for (int j = 0; j < 2; ++j) {
            int g = gp * 2 + j;
            int b = b0 + g;
            if (b < B)
                out[(size_t)b * 256 + o] = (xg[j] - muS[g]) * rsS[g] * gm + bt;
        }
    }
}

extern "C" void kernel_launch(void* const* d_in, const int* in_sizes, int n_in,
                              void* d_out, int out_size) {
    (void)n_in; (void)out_size;
    const float* node  = (const float*)d_in[0];
    const float* timef = (const float*)d_in[1];
    const float* edge  = (const float*)d_in[2];
    const float* nnode = (const float*)d_in[3];
    const float* ntime = (const float*)d_in[4];
    const int*   mask  = (const int*)d_in[5];
    const float* WQ    = (const float*)d_in[6];
    const float* WKV   = (const float*)d_in[7];
    const float* WO    = (const float*)d_in[8];
    const float* bO    = (const float*)d_in[9];
    const float* gamma = (const float*)d_in[10];
    const float* beta  = (const float*)d_in[11];
    float* out = (float*)d_out;

    int B = in_sizes[0] / 128;
    int blocks = (B + G - 1) / G;

    cudaFuncSetAttribute(ta_kernel, cudaFuncAttributeMaxDynamicSharedMemorySize, SMEM_BYTES);
    ta_kernel<<<blocks, NT, SMEM_BYTES>>>(node, timef, edge, nnode, ntime, mask,
                                          WQ, WKV, WO, bO, gamma, beta, out, B);
}